// round 13
// baseline (speedup 1.0000x reference)
#include <cuda_runtime.h>

// UnfoldMatmulFold, fused gather. 4x4-px tile, CV=1 channel/thread, TPB=768
// (thread t <-> channel t; 2 warps per head, weight LDS still warp-uniform).
//
// out[b,y,x,c] = sum over (h,kh),(w,kw) with 2h+kh=y+1, 2w+kw=x+1 of
//   sum_q attn[b,h,w,n,p=(kh,kw),q=(qh,qw)] * vv[b,2h+qh-1,2w+qw-1,c]
//
// Block = (b, ty, tx): output rows 4ty..4ty+3, cols 4tx..4tx+3.
// attn staged to smem [patch][n][p][qh][4]: a qw-triple is one LDS.128.

namespace {

constexpr int Hc  = 28;
constexpr int Wc  = 28;
constexpr int Cch = 768;
constexpr int NH  = 12;
constexpr int GH  = 14;
constexpr int TPB = 768;                // thread == channel
constexpr int SEG = NH * 81;            // 972 floats per (b,h,w)
constexpr int SEG4 = SEG / 4;           // 243 float4s
constexpr int PATCH_W  = 9 * 3 * 4;     // 108 padded weights per head
constexpr int PATCH_SZ = NH * PATCH_W;  // 1296

// Row tables (R=4, verified in round 7): per vv row r (0..6),
// entries (ph, qh, kh, oy), constraint 2*ph + qh = r.
__device__ constexpr int RN [7]    = {2,2,5,3,4,1,1};
__device__ constexpr int RPH[7][5] = {{0,0,0,0,0},{0,0,0,0,0},{0,0,1,1,1},
                                      {1,1,1,0,0},{1,1,1,2,0},{2,0,0,0,0},{2,0,0,0,0}};
__device__ constexpr int RQH[7][5] = {{0,0,0,0,0},{1,1,0,0,0},{2,2,0,0,0},
                                      {1,1,1,0,0},{2,2,2,0,0},{1,0,0,0,0},{2,0,0,0,0}};
__device__ constexpr int RKH[7][5] = {{1,2,0,0,0},{1,2,0,0,0},{1,2,0,1,2},
                                      {0,1,2,0,0},{0,1,2,0,0},{0,0,0,0,0},{0,0,0,0,0}};
__device__ constexpr int ROY[7][5] = {{0,1,0,0,0},{0,1,0,0,0},{0,1,1,2,3},
                                      {1,2,3,0,0},{1,2,3,3,0},{3,0,0,0,0},{3,0,0,0,0}};

// Col tables (C=4): per patch-col pw, entries (kw, ox)
__device__ constexpr int CN [3]    = {2,3,1};
__device__ constexpr int CKW[3][3] = {{1,2,0},{0,1,2},{0,0,0}};
__device__ constexpr int COX[3][3] = {{0,1,0},{1,2,3},{3,0,0}};

__global__ __launch_bounds__(TPB, 2)
void fused_ufmf_kernel(const float* __restrict__ vv,
                       const float* __restrict__ attn,
                       float* __restrict__ out)
{
    const int t  = threadIdx.x;             // 0..767 == channel
    const int tx = blockIdx.x;              // 0..6
    const int ty = blockIdx.y;              // 0..6
    const int b  = blockIdx.z;

    const int y0 = 4 * ty;
    const int x0 = 4 * tx;

    __shared__ __align__(16) float s_w[9 * PATCH_SZ];   // 46656 B

    // ---- Stage attn for 9 patches (threads 0..242; indices hoisted) ----
    if (t < SEG4) {
        int dst[4];
#pragma unroll
        for (int j = 0; j < 4; ++j) {
            const int i   = 4 * t + j;
            const int nn  = i / 81;
            const int rem = i - nn * 81;
            const int p   = rem / 9;
            const int q   = rem - p * 9;
            dst[j] = nn * PATCH_W + p * 12 + q + q / 3;
        }
#pragma unroll
        for (int patch = 0; patch < 9; ++patch) {
            const int ph = patch / 3, pw = patch % 3;
            const int h = 2 * ty + ph, w = 2 * tx + pw;
            const bool val = (h < GH) && (w < GH);
            const int hs = val ? h : 0, ws = val ? w : 0;
            const float4* g4 = reinterpret_cast<const float4*>(
                attn + ((size_t)((b * GH + hs) * GH + ws)) * SEG);
            float4 x4 = make_float4(0.f, 0.f, 0.f, 0.f);
            if (val) x4 = __ldg(g4 + t);
            float* sp = s_w + patch * PATCH_SZ;
            sp[dst[0]] = x4.x; sp[dst[1]] = x4.y;
            sp[dst[2]] = x4.z; sp[dst[3]] = x4.w;
        }
    }
    __syncthreads();

    float acc[4][4];
#pragma unroll
    for (int i = 0; i < 4; ++i)
#pragma unroll
        for (int j = 0; j < 4; ++j) acc[i][j] = 0.0f;

    const float* vbase = vv + (size_t)b * (Hc * Wc * Cch) + t;
    const float* swn   = s_w + (t >> 6) * PATCH_W;       // head = t/64

#pragma unroll
    for (int r = 0; r < 7; ++r) {
        const int gy = y0 - 1 + r;
        const bool rok = (unsigned)gy < (unsigned)Hc;

        float v[7];
#pragma unroll
        for (int s = 0; s < 7; ++s) {
            const int gx = x0 - 1 + s;
            v[s] = (rok && ((unsigned)gx < (unsigned)Wc))
                 ? vbase[(unsigned)((gy * Wc + gx) * Cch)]
                 : 0.0f;
        }

#pragma unroll
        for (int e = 0; e < RN[r]; ++e) {
            const int ph = RPH[r][e], qh = RQH[r][e];
            const int kh = RKH[r][e], oy = ROY[r][e];
#pragma unroll
            for (int pw = 0; pw < 3; ++pw) {
#pragma unroll
                for (int f = 0; f < CN[pw]; ++f) {
                    const int kw = CKW[pw][f], ox = COX[pw][f];
                    const float4 w4 = *reinterpret_cast<const float4*>(
                        swn + (ph * 3 + pw) * PATCH_SZ
                            + (kh * 3 + kw) * 12 + qh * 4);
                    acc[oy][ox] += w4.x * v[2*pw]
                                 + w4.y * v[2*pw+1]
                                 + w4.z * v[2*pw+2];
                }
            }
        }
    }

    // ---- Stores: each output element produced exactly once ----
    float* obase = out + (size_t)b * (Hc * Wc * Cch)
                       + (unsigned)((y0 * Wc + x0) * Cch) + t;
#pragma unroll
    for (int oy = 0; oy < 4; ++oy)
#pragma unroll
        for (int ox = 0; ox < 4; ++ox)
            obase[(unsigned)((oy * Wc + ox) * Cch)] = acc[oy][ox];
}

} // namespace

extern "C" void kernel_launch(void* const* d_in, const int* in_sizes, int n_in,
                              void* d_out, int out_size)
{
    const float* vv   = (const float*)d_in[0];
    const float* attn = (const float*)d_in[1];
    float* out        = (float*)d_out;

    dim3 grid(7, 7, 64);    // (tx, ty, b) 4x4 tiles
    fused_ufmf_kernel<<<grid, TPB>>>(vv, attn, out);
}

// round 14
// speedup vs baseline: 1.3236x; 1.3236x over previous
#include <cuda_runtime.h>

// UnfoldMatmulFold, fused gather. 2x4-px tile, CV=2, TPB=384 (warp==head).
// R6 kernel (established optimum across 13 rounds) + 3D grid (only delta).
//
// out[b,y,x,c] = sum over (h,kh),(w,kw) with 2h+kh=y+1, 2w+kw=x+1 of
//   sum_q attn[b,h,w,n,p=(kh,kw),q=(qh,qw)] * vv[b,2h+qh-1,2w+qw-1,c]
//
// attn staged to smem [patch][n][p][qh][4]: a qw-triple is one LDS.128.

namespace {

constexpr int Hc  = 28;
constexpr int Wc  = 28;
constexpr int Cch = 768;
constexpr int NH  = 12;
constexpr int GH  = 14;
constexpr int TPB = 384;                // 12 warps = 12 heads
constexpr int SEG = NH * 81;            // 972 floats per (b,h,w)
constexpr int SEG4 = SEG / 4;           // 243 float4s
constexpr int PATCH_W  = 9 * 3 * 4;     // 108 padded weights per head
constexpr int PATCH_SZ = NH * PATCH_W;  // 1296

// Row tables: per vv row r, entries (ph, qh, kh, oy)
__device__ constexpr int RN [5]    = {2,2,3,1,1};
__device__ constexpr int RPH[5][3] = {{0,0,0},{0,0,0},{0,0,1},{1,0,0},{1,0,0}};
__device__ constexpr int RQH[5][3] = {{0,0,0},{1,1,0},{2,2,0},{1,0,0},{2,0,0}};
__device__ constexpr int RKH[5][3] = {{1,2,0},{1,2,0},{1,2,0},{0,0,0},{0,0,0}};
__device__ constexpr int ROY[5][3] = {{0,1,0},{0,1,0},{0,1,1},{1,0,0},{1,0,0}};

// Col tables: per patch-col pw, entries (kw, ox)
__device__ constexpr int CN [3]    = {2,3,1};
__device__ constexpr int CKW[3][3] = {{1,2,0},{0,1,2},{0,0,0}};
__device__ constexpr int COX[3][3] = {{0,1,0},{1,2,3},{3,0,0}};

__global__ __launch_bounds__(TPB, 3)
void fused_ufmf_kernel(const float* __restrict__ vv,
                       const float* __restrict__ attn,
                       float* __restrict__ out)
{
    const int t    = threadIdx.x;           // 0..383
    const int tqx  = blockIdx.x;            // 0..6
    const int qy   = blockIdx.y;            // 0..13
    const int b    = blockIdx.z;

    const int y0   = 2 * qy;
    const int x0   = 4 * tqx;
    const int n    = t >> 5;                // head == warp id
    const int lane = t & 31;
    const int c0   = n * 64 + lane * 2;     // 2 channels per thread

    __shared__ __align__(16) float s_w[6 * PATCH_SZ];   // 31104 B

    // ---- Stage attn (threads 0..242 active; scatter indices hoisted) ----
    if (t < SEG4) {
        int dst[4];
#pragma unroll
        for (int j = 0; j < 4; ++j) {
            const int i   = 4 * t + j;
            const int nn  = i / 81;
            const int rem = i - nn * 81;
            const int p   = rem / 9;
            const int q   = rem - p * 9;
            dst[j] = nn * PATCH_W + p * 12 + q + q / 3;
        }
#pragma unroll
        for (int patch = 0; patch < 6; ++patch) {
            const int ph = patch / 3, pw = patch % 3;
            const int h = qy + ph, w = 2 * tqx + pw;
            const bool val = (h < GH) && (w < GH);
            const int hs = val ? h : 0, ws = val ? w : 0;
            const float4* g4 = reinterpret_cast<const float4*>(
                attn + ((size_t)((b * GH + hs) * GH + ws)) * SEG);
            float4 x4 = make_float4(0.f, 0.f, 0.f, 0.f);
            if (val) x4 = __ldg(g4 + t);
            float* sp = s_w + patch * PATCH_SZ;
            sp[dst[0]] = x4.x; sp[dst[1]] = x4.y;
            sp[dst[2]] = x4.z; sp[dst[3]] = x4.w;
        }
    }
    __syncthreads();

    float2 acc[2][4];
#pragma unroll
    for (int i = 0; i < 2; ++i)
#pragma unroll
        for (int j = 0; j < 4; ++j) acc[i][j] = make_float2(0.f, 0.f);

    const float* vbase = vv + (size_t)b * Hc * Wc * Cch + c0;
    const float* swn   = s_w + n * PATCH_W;

#pragma unroll
    for (int r = 0; r < 5; ++r) {
        const int gy = y0 - 1 + r;
        const bool rok = (unsigned)gy < (unsigned)Hc;

        float2 v[7];
#pragma unroll
        for (int s = 0; s < 7; ++s) {
            const int gx = x0 - 1 + s;
            if (rok && ((unsigned)gx < (unsigned)Wc))
                v[s] = *reinterpret_cast<const float2*>(
                    vbase + ((size_t)gy * Wc + gx) * Cch);
            else
                v[s] = make_float2(0.f, 0.f);
        }

#pragma unroll
        for (int pw = 0; pw < 3; ++pw) {
#pragma unroll
            for (int e = 0; e < RN[r]; ++e) {
                const int ph = RPH[r][e], qh = RQH[r][e];
                const int kh = RKH[r][e], oy = ROY[r][e];
#pragma unroll
                for (int f = 0; f < CN[pw]; ++f) {
                    const int kw = CKW[pw][f], ox = COX[pw][f];
                    const float4 w4 = *reinterpret_cast<const float4*>(
                        swn + (ph * 3 + pw) * PATCH_SZ
                            + (kh * 3 + kw) * 12 + qh * 4);
                    float2& a = acc[oy][ox];
                    a.x += w4.x * v[2*pw  ].x;  a.y += w4.x * v[2*pw  ].y;
                    a.x += w4.y * v[2*pw+1].x;  a.y += w4.y * v[2*pw+1].y;
                    a.x += w4.z * v[2*pw+2].x;  a.y += w4.z * v[2*pw+2].y;
                }
            }
        }
    }

    // ---- Stores: each output element produced exactly once ----
#pragma unroll
    for (int oy = 0; oy < 2; ++oy)
#pragma unroll
        for (int ox = 0; ox < 4; ++ox)
            *reinterpret_cast<float2*>(
                out + ((size_t)((b * Hc + (y0 + oy)) * Wc + (x0 + ox))) * Cch + c0)
                = acc[oy][ox];
}

} // namespace

extern "C" void kernel_launch(void* const* d_in, const int* in_sizes, int n_in,
                              void* d_out, int out_size)
{
    const float* vv   = (const float*)d_in[0];
    const float* attn = (const float*)d_in[1];
    float* out        = (float*)d_out;

    dim3 grid(7, 14, 64);   // (tqx, qy, b)
    fused_ufmf_kernel<<<grid, TPB>>>(vv, attn, out);
}

// round 15
// speedup vs baseline: 1.3725x; 1.0369x over previous
#include <cuda_runtime.h>

// UnfoldMatmulFold, fused gather. 2x4-px tile per block, CV=2 channels/thread,
// TPB=384 (one warp per head -> warp-uniform weight smem loads).
// FINAL: R6 configuration verbatim, the measured optimum across 14 rounds
// (2D grid(98,64) launch shape is load-bearing: 3D (7,14,64) costs ~4us).
//
// out[b,y,x,c] = sum over (h,kh),(w,kw) with 2h+kh=y+1, 2w+kw=x+1 of
//   sum_q attn[b,h,w,n,p=(kh,kw),q=(qh,qw)] * vv[b,2h+qh-1,2w+qw-1,c]
//
// attn staged to smem [patch][n][p][qh][4]: a qw-triple is one LDS.128.

namespace {

constexpr int Hc  = 28;
constexpr int Wc  = 28;
constexpr int Cch = 768;
constexpr int NH  = 12;
constexpr int GH  = 14;
constexpr int TPB = 384;                // 12 warps = 12 heads
constexpr int SEG = NH * 81;            // 972 floats per (b,h,w)
constexpr int SEG4 = SEG / 4;           // 243 float4s
constexpr int PATCH_W  = 9 * 3 * 4;     // 108 padded weights per head
constexpr int PATCH_SZ = NH * PATCH_W;  // 1296

// Row tables: per vv row r, entries (ph, qh, kh, oy)
__device__ constexpr int RN [5]    = {2,2,3,1,1};
__device__ constexpr int RPH[5][3] = {{0,0,0},{0,0,0},{0,0,1},{1,0,0},{1,0,0}};
__device__ constexpr int RQH[5][3] = {{0,0,0},{1,1,0},{2,2,0},{1,0,0},{2,0,0}};
__device__ constexpr int RKH[5][3] = {{1,2,0},{1,2,0},{1,2,0},{0,0,0},{0,0,0}};
__device__ constexpr int ROY[5][3] = {{0,1,0},{0,1,0},{0,1,1},{1,0,0},{1,0,0}};

// Col tables: per patch-col pw, entries (kw, ox)
__device__ constexpr int CN [3]    = {2,3,1};
__device__ constexpr int CKW[3][3] = {{1,2,0},{0,1,2},{0,0,0}};
__device__ constexpr int COX[3][3] = {{0,1,0},{1,2,3},{3,0,0}};

__global__ __launch_bounds__(TPB, 3)
void fused_ufmf_kernel(const float* __restrict__ vv,
                       const float* __restrict__ attn,
                       float* __restrict__ out)
{
    const int t    = threadIdx.x;           // 0..383
    const int qy   = blockIdx.x / 7;        // 0..13
    const int tqx  = blockIdx.x % 7;        // 0..6
    const int b    = blockIdx.y;

    const int y0   = 2 * qy;
    const int x0   = 4 * tqx;
    const int n    = t >> 5;                // head == warp id
    const int lane = t & 31;
    const int c0   = n * 64 + lane * 2;     // 2 channels per thread

    __shared__ __align__(16) float s_w[6 * PATCH_SZ];   // 31104 B

    // ---- Stage attn (threads 0..242 active; scatter indices hoisted) ----
    if (t < SEG4) {
        int dst[4];
#pragma unroll
        for (int j = 0; j < 4; ++j) {
            const int i   = 4 * t + j;
            const int nn  = i / 81;
            const int rem = i - nn * 81;
            const int p   = rem / 9;
            const int q   = rem - p * 9;
            dst[j] = nn * PATCH_W + p * 12 + q + q / 3;
        }
#pragma unroll
        for (int patch = 0; patch < 6; ++patch) {
            const int ph = patch / 3, pw = patch % 3;
            const int h = qy + ph, w = 2 * tqx + pw;
            const bool val = (h < GH) && (w < GH);
            const int hs = val ? h : 0, ws = val ? w : 0;
            const float4* g4 = reinterpret_cast<const float4*>(
                attn + ((size_t)((b * GH + hs) * GH + ws)) * SEG);
            float4 x4 = make_float4(0.f, 0.f, 0.f, 0.f);
            if (val) x4 = __ldg(g4 + t);
            float* sp = s_w + patch * PATCH_SZ;
            sp[dst[0]] = x4.x; sp[dst[1]] = x4.y;
            sp[dst[2]] = x4.z; sp[dst[3]] = x4.w;
        }
    }
    __syncthreads();

    float2 acc[2][4];
#pragma unroll
    for (int i = 0; i < 2; ++i)
#pragma unroll
        for (int j = 0; j < 4; ++j) acc[i][j] = make_float2(0.f, 0.f);

    const float* vbase = vv + (size_t)b * Hc * Wc * Cch + c0;
    const float* swn   = s_w + n * PATCH_W;

#pragma unroll
    for (int r = 0; r < 5; ++r) {
        const int gy = y0 - 1 + r;
        const bool rok = (unsigned)gy < (unsigned)Hc;

        float2 v[7];
#pragma unroll
        for (int s = 0; s < 7; ++s) {
            const int gx = x0 - 1 + s;
            if (rok && ((unsigned)gx < (unsigned)Wc))
                v[s] = *reinterpret_cast<const float2*>(
                    vbase + ((size_t)gy * Wc + gx) * Cch);
            else
                v[s] = make_float2(0.f, 0.f);
        }

#pragma unroll
        for (int pw = 0; pw < 3; ++pw) {
#pragma unroll
            for (int e = 0; e < RN[r]; ++e) {
                const int ph = RPH[r][e], qh = RQH[r][e];
                const int kh = RKH[r][e], oy = ROY[r][e];
#pragma unroll
                for (int f = 0; f < CN[pw]; ++f) {
                    const int kw = CKW[pw][f], ox = COX[pw][f];
                    const float4 w4 = *reinterpret_cast<const float4*>(
                        swn + (ph * 3 + pw) * PATCH_SZ
                            + (kh * 3 + kw) * 12 + qh * 4);
                    float2& a = acc[oy][ox];
                    a.x += w4.x * v[2*pw  ].x;  a.y += w4.x * v[2*pw  ].y;
                    a.x += w4.y * v[2*pw+1].x;  a.y += w4.y * v[2*pw+1].y;
                    a.x += w4.z * v[2*pw+2].x;  a.y += w4.z * v[2*pw+2].y;
                }
            }
        }
    }

    // ---- Stores: each output element produced exactly once ----
#pragma unroll
    for (int oy = 0; oy < 2; ++oy)
#pragma unroll
        for (int ox = 0; ox < 4; ++ox) {
            *reinterpret_cast<float2*>(
                out + ((size_t)((b * Hc + (y0 + oy)) * Wc + (x0 + ox))) * Cch + c0)
                = acc[oy][ox];
        }
}

} // namespace

extern "C" void kernel_launch(void* const* d_in, const int* in_sizes, int n_in,
                              void* d_out, int out_size)
{
    const float* vv   = (const float*)d_in[0];
    const float* attn = (const float*)d_in[1];
    float* out        = (float*)d_out;

    dim3 grid(14 * 7, 64);   // (qy,tqx) tiles x batch — 2D shape is load-bearing
    fused_ufmf_kernel<<<grid, TPB>>>(vv, attn, out);
}

// round 16
// speedup vs baseline: 1.3730x; 1.0003x over previous
#include <cuda_runtime.h>

// UnfoldMatmulFold, fused gather. 2x4-px tile per block, CV=2 channels/thread,
// TPB=384 (one warp per head -> warp-uniform weight smem loads).
// R6 optimum (2D grid(98,64) load-bearing) + ONE isolated delta: __stcs on
// output stores (out is write-once; evict-first keeps L2 for vv/attn reuse).
//
// out[b,y,x,c] = sum over (h,kh),(w,kw) with 2h+kh=y+1, 2w+kw=x+1 of
//   sum_q attn[b,h,w,n,p=(kh,kw),q=(qh,qw)] * vv[b,2h+qh-1,2w+qw-1,c]
//
// attn staged to smem [patch][n][p][qh][4]: a qw-triple is one LDS.128.

namespace {

constexpr int Hc  = 28;
constexpr int Wc  = 28;
constexpr int Cch = 768;
constexpr int NH  = 12;
constexpr int GH  = 14;
constexpr int TPB = 384;                // 12 warps = 12 heads
constexpr int SEG = NH * 81;            // 972 floats per (b,h,w)
constexpr int SEG4 = SEG / 4;           // 243 float4s
constexpr int PATCH_W  = 9 * 3 * 4;     // 108 padded weights per head
constexpr int PATCH_SZ = NH * PATCH_W;  // 1296

// Row tables: per vv row r, entries (ph, qh, kh, oy)
__device__ constexpr int RN [5]    = {2,2,3,1,1};
__device__ constexpr int RPH[5][3] = {{0,0,0},{0,0,0},{0,0,1},{1,0,0},{1,0,0}};
__device__ constexpr int RQH[5][3] = {{0,0,0},{1,1,0},{2,2,0},{1,0,0},{2,0,0}};
__device__ constexpr int RKH[5][3] = {{1,2,0},{1,2,0},{1,2,0},{0,0,0},{0,0,0}};
__device__ constexpr int ROY[5][3] = {{0,1,0},{0,1,0},{0,1,1},{1,0,0},{1,0,0}};

// Col tables: per patch-col pw, entries (kw, ox)
__device__ constexpr int CN [3]    = {2,3,1};
__device__ constexpr int CKW[3][3] = {{1,2,0},{0,1,2},{0,0,0}};
__device__ constexpr int COX[3][3] = {{0,1,0},{1,2,3},{3,0,0}};

__global__ __launch_bounds__(TPB, 3)
void fused_ufmf_kernel(const float* __restrict__ vv,
                       const float* __restrict__ attn,
                       float* __restrict__ out)
{
    const int t    = threadIdx.x;           // 0..383
    const int qy   = blockIdx.x / 7;        // 0..13
    const int tqx  = blockIdx.x % 7;        // 0..6
    const int b    = blockIdx.y;

    const int y0   = 2 * qy;
    const int x0   = 4 * tqx;
    const int n    = t >> 5;                // head == warp id
    const int lane = t & 31;
    const int c0   = n * 64 + lane * 2;     // 2 channels per thread

    __shared__ __align__(16) float s_w[6 * PATCH_SZ];   // 31104 B

    // ---- Stage attn (threads 0..242 active; scatter indices hoisted) ----
    if (t < SEG4) {
        int dst[4];
#pragma unroll
        for (int j = 0; j < 4; ++j) {
            const int i   = 4 * t + j;
            const int nn  = i / 81;
            const int rem = i - nn * 81;
            const int p   = rem / 9;
            const int q   = rem - p * 9;
            dst[j] = nn * PATCH_W + p * 12 + q + q / 3;
        }
#pragma unroll
        for (int patch = 0; patch < 6; ++patch) {
            const int ph = patch / 3, pw = patch % 3;
            const int h = qy + ph, w = 2 * tqx + pw;
            const bool val = (h < GH) && (w < GH);
            const int hs = val ? h : 0, ws = val ? w : 0;
            const float4* g4 = reinterpret_cast<const float4*>(
                attn + ((size_t)((b * GH + hs) * GH + ws)) * SEG);
            float4 x4 = make_float4(0.f, 0.f, 0.f, 0.f);
            if (val) x4 = __ldg(g4 + t);     // default policy: attn has reuse
            float* sp = s_w + patch * PATCH_SZ;
            sp[dst[0]] = x4.x; sp[dst[1]] = x4.y;
            sp[dst[2]] = x4.z; sp[dst[3]] = x4.w;
        }
    }
    __syncthreads();

    float2 acc[2][4];
#pragma unroll
    for (int i = 0; i < 2; ++i)
#pragma unroll
        for (int j = 0; j < 4; ++j) acc[i][j] = make_float2(0.f, 0.f);

    const float* vbase = vv + (size_t)b * Hc * Wc * Cch + c0;
    const float* swn   = s_w + n * PATCH_W;

#pragma unroll
    for (int r = 0; r < 5; ++r) {
        const int gy = y0 - 1 + r;
        const bool rok = (unsigned)gy < (unsigned)Hc;

        float2 v[7];
#pragma unroll
        for (int s = 0; s < 7; ++s) {
            const int gx = x0 - 1 + s;
            if (rok && ((unsigned)gx < (unsigned)Wc))
                v[s] = *reinterpret_cast<const float2*>(
                    vbase + ((size_t)gy * Wc + gx) * Cch);
            else
                v[s] = make_float2(0.f, 0.f);
        }

#pragma unroll
        for (int pw = 0; pw < 3; ++pw) {
#pragma unroll
            for (int e = 0; e < RN[r]; ++e) {
                const int ph = RPH[r][e], qh = RQH[r][e];
                const int kh = RKH[r][e], oy = ROY[r][e];
#pragma unroll
                for (int f = 0; f < CN[pw]; ++f) {
                    const int kw = CKW[pw][f], ox = COX[pw][f];
                    const float4 w4 = *reinterpret_cast<const float4*>(
                        swn + (ph * 3 + pw) * PATCH_SZ
                            + (kh * 3 + kw) * 12 + qh * 4);
                    float2& a = acc[oy][ox];
                    a.x += w4.x * v[2*pw  ].x;  a.y += w4.x * v[2*pw  ].y;
                    a.x += w4.y * v[2*pw+1].x;  a.y += w4.y * v[2*pw+1].y;
                    a.x += w4.z * v[2*pw+2].x;  a.y += w4.z * v[2*pw+2].y;
                }
            }
        }
    }

    // ---- Streaming stores: out is write-once, keep L2 for vv/attn ----
#pragma unroll
    for (int oy = 0; oy < 2; ++oy)
#pragma unroll
        for (int ox = 0; ox < 4; ++ox)
            __stcs(reinterpret_cast<float2*>(
                       out + ((size_t)((b * Hc + (y0 + oy)) * Wc + (x0 + ox))) * Cch + c0),
                   acc[oy][ox]);
}

} // namespace

extern "C" void kernel_launch(void* const* d_in, const int* in_sizes, int n_in,
                              void* d_out, int out_size)
{
    const float* vv   = (const float*)d_in[0];
    const float* attn = (const float*)d_in[1];
    float* out        = (float*)d_out;

    dim3 grid(14 * 7, 64);   // (qy,tqx) tiles x batch — 2D shape is load-bearing
    fused_ufmf_kernel<<<grid, TPB>>>(vv, attn, out);
}